// round 1
// baseline (speedup 1.0000x reference)
#include <cuda_runtime.h>
#include <math.h>

#define NN   50000
#define EE   1600000
#define FIN  128
#define HH   32
#define CC   16

// ---------------- device scratch (no allocs allowed) ----------------
__device__ float g_dinv[NN];
__device__ int   g_count[NN];
__device__ int   g_rowptr[NN + 1];
__device__ int   g_cursor[NN];
__device__ int   g_col[EE];
__device__ float g_bufA[NN * HH];   // xw_scaled (layer1), then xw2_scaled (layer2)
__device__ float g_bufB[NN * HH];   // h1

// ---------------- CSR build ----------------
__global__ void k_zero_count() {
    int i = blockIdx.x * blockDim.x + threadIdx.x;
    if (i < NN) g_count[i] = 0;
}

__global__ void k_hist(const int* __restrict__ ei) {
    int e = blockIdx.x * blockDim.x + threadIdx.x;
    if (e < EE) atomicAdd(&g_count[ei[EE + e]], 1);
}

// single-block exclusive scan over g_count -> rowptr/cursor, plus dinv = rsqrt(deg+1)
__global__ void k_scan() {
    __shared__ int warp_sums[32];
    __shared__ int s_carry;
    int t = threadIdx.x, lane = t & 31, w = t >> 5;
    if (t == 0) s_carry = 0;
    __syncthreads();
    for (int base = 0; base < NN; base += 1024) {
        int i = base + t;
        int v = (i < NN) ? g_count[i] : 0;
        int incl = v;
        #pragma unroll
        for (int off = 1; off < 32; off <<= 1) {
            int y = __shfl_up_sync(0xffffffffu, incl, off);
            if (lane >= off) incl += y;
        }
        if (lane == 31) warp_sums[w] = incl;
        __syncthreads();
        if (w == 0) {
            int si = warp_sums[lane];
            #pragma unroll
            for (int off = 1; off < 32; off <<= 1) {
                int y = __shfl_up_sync(0xffffffffu, si, off);
                if (lane >= off) si += y;
            }
            warp_sums[lane] = si;   // inclusive warp totals
        }
        __syncthreads();
        int wbase = (w > 0) ? warp_sums[w - 1] : 0;
        int excl  = s_carry + wbase + incl - v;
        if (i < NN) {
            g_rowptr[i] = excl;
            g_cursor[i] = excl;
            g_dinv[i]   = rsqrtf((float)(v + 1));   // +1 self loop, always > 0
        }
        __syncthreads();
        if (t == 1023) s_carry += warp_sums[31];
        __syncthreads();
    }
    if (t == 0) g_rowptr[NN] = s_carry;
}

__global__ void k_scatter(const int* __restrict__ ei) {
    int e = blockIdx.x * blockDim.x + threadIdx.x;
    if (e < EE) {
        int s = ei[e];
        int d = ei[EE + e];
        int p = atomicAdd(&g_cursor[d], 1);
        g_col[p] = s;
    }
}

// ---------------- GEMM1: bufA = (x @ W1) * dinv[row] ----------------
__global__ void __launch_bounds__(256) k_gemm1(const float* __restrict__ x,
                                               const float* __restrict__ W1) {
    __shared__ float sW[FIN * HH];        // 16 KB
    __shared__ float sx[8][FIN];          // 4 KB
    int t = threadIdx.x, lane = t & 31, w = t >> 5;
    for (int i = t; i < FIN * HH; i += 256) sW[i] = W1[i];
    __syncthreads();
    float* __restrict__ outp = g_bufA;
    const float* __restrict__ dinv = g_dinv;
    int nwarps = gridDim.x * 8;
    for (int row = blockIdx.x * 8 + w; row < NN; row += nwarps) {
        const float4* xr = (const float4*)(x + (size_t)row * FIN);
        float4 v = xr[lane];
        ((float4*)sx[w])[lane] = v;
        __syncwarp();
        float acc = 0.f;
        #pragma unroll 16
        for (int k = 0; k < FIN; k++)
            acc += sx[w][k] * sW[k * HH + lane];
        outp[row * HH + lane] = acc * dinv[row];
        __syncwarp();
    }
}

// ---------------- aggregation core (warp per node) ----------------
__device__ __forceinline__ float agg_node(const float* __restrict__ src, int i, int lane) {
    const int* __restrict__ rp  = g_rowptr;
    const int* __restrict__ col = g_col;
    int beg = rp[i], end = rp[i + 1];
    float acc = src[i * HH + lane];        // self loop (dinv[src] already folded in)
    int e = beg;
    while (end - e >= 32) {
        int idx = col[e + lane];
        float a0 = 0.f, a1 = 0.f, a2 = 0.f, a3 = 0.f;
        #pragma unroll
        for (int k = 0; k < 32; k += 4) {
            int s0 = __shfl_sync(0xffffffffu, idx, k);
            int s1 = __shfl_sync(0xffffffffu, idx, k + 1);
            int s2 = __shfl_sync(0xffffffffu, idx, k + 2);
            int s3 = __shfl_sync(0xffffffffu, idx, k + 3);
            a0 += src[s0 * HH + lane];
            a1 += src[s1 * HH + lane];
            a2 += src[s2 * HH + lane];
            a3 += src[s3 * HH + lane];
        }
        acc += (a0 + a1) + (a2 + a3);
        e += 32;
    }
    int m = end - e;
    if (m > 0) {
        int idx = (lane < m) ? col[e + lane] : 0;
        for (int k = 0; k < m; k++) {
            int s = __shfl_sync(0xffffffffu, idx, k);
            acc += src[s * HH + lane];
        }
    }
    return acc;
}

// layer1 aggregate: bufB = tanh(dinv[i]*sum + b1)
__global__ void __launch_bounds__(256) k_agg1(const float* __restrict__ b1) {
    int warp = (blockIdx.x * blockDim.x + threadIdx.x) >> 5;
    int lane = threadIdx.x & 31;
    if (warp >= NN) return;
    int i = warp;
    float acc = agg_node(g_bufA, i, lane);
    g_bufB[i * HH + lane] = tanhf(g_dinv[i] * acc + b1[lane]);
}

// ---------------- GEMM2: bufA = (bufB @ W2) * dinv[row] ----------------
__global__ void __launch_bounds__(256) k_gemm2(const float* __restrict__ W2) {
    __shared__ float sW[HH * HH];
    int t = threadIdx.x, lane = t & 31, w = t >> 5;
    for (int i = t; i < HH * HH; i += 256) sW[i] = W2[i];
    __syncthreads();
    const float* __restrict__ inp  = g_bufB;
    float* __restrict__ outp = g_bufA;
    const float* __restrict__ dinv = g_dinv;
    int nwarps = gridDim.x * 8;
    for (int row = blockIdx.x * 8 + w; row < NN; row += nwarps) {
        float hv  = inp[row * HH + lane];
        float acc = 0.f;
        #pragma unroll
        for (int k = 0; k < HH; k++) {
            float hk = __shfl_sync(0xffffffffu, hv, k);
            acc += hk * sW[k * HH + lane];
        }
        outp[row * HH + lane] = acc * dinv[row];
    }
}

// layer2 aggregate + tanh + fused classifier.
// out layout: [ logits (NN*CC) | h (NN*HH) ]
__global__ void __launch_bounds__(256) k_agg2(const float* __restrict__ b2,
                                              const float* __restrict__ Wc,
                                              const float* __restrict__ bc,
                                              float* __restrict__ out) {
    __shared__ float sWc[HH * CC];
    __shared__ float sbc[CC];
    int t = threadIdx.x;
    for (int i = t; i < HH * CC; i += 256) sWc[i] = Wc[i];
    if (t < CC) sbc[t] = bc[t];
    __syncthreads();
    int warp = (blockIdx.x * blockDim.x + t) >> 5;
    int lane = t & 31;
    if (warp >= NN) return;
    int i = warp;
    float acc = agg_node(g_bufA, i, lane);
    float h = tanhf(g_dinv[i] * acc + b2[lane]);
    out[NN * CC + i * HH + lane] = h;
    // classifier: lanes 0..15 compute one class each (lanes 16..31 shadow lane&15)
    float o = 0.f;
    int c = lane & 15;
    #pragma unroll
    for (int k = 0; k < HH; k++) {
        float hk = __shfl_sync(0xffffffffu, h, k);
        o += hk * sWc[k * CC + c];
    }
    if (lane < CC) out[i * CC + lane] = o + sbc[lane];
}

// ---------------- launch ----------------
extern "C" void kernel_launch(void* const* d_in, const int* in_sizes, int n_in,
                              void* d_out, int out_size) {
    const float* x  = (const float*)d_in[0];
    const int*   ei = (const int*)  d_in[1];
    const float* W1 = (const float*)d_in[2];
    const float* b1 = (const float*)d_in[3];
    const float* W2 = (const float*)d_in[4];
    const float* b2 = (const float*)d_in[5];
    const float* Wc = (const float*)d_in[6];
    const float* bc = (const float*)d_in[7];
    float* out = (float*)d_out;

    k_zero_count<<<(NN + 255) / 256, 256>>>();
    k_hist<<<(EE + 255) / 256, 256>>>(ei);
    k_scan<<<1, 1024>>>();
    k_scatter<<<(EE + 255) / 256, 256>>>(ei);
    k_gemm1<<<1184, 256>>>(x, W1);
    k_agg1<<<(NN * 32 + 255) / 256, 256>>>(b1);
    k_gemm2<<<1184, 256>>>(W2);
    k_agg2<<<(NN * 32 + 255) / 256, 256>>>(b2, Wc, bc, out);
}

// round 2
// speedup vs baseline: 1.3563x; 1.3563x over previous
#include <cuda_runtime.h>
#include <math.h>

#define NN   50000
#define EE   1600000
#define FIN  128
#define HH   32
#define CC   16
#define NB_SCAN 49          // ceil(50000/1024)

// ---------------- device scratch (no allocs allowed) ----------------
__device__ float g_dinv[NN];
__device__ int   g_count[NN];          // zero-init (BSS); re-zeroed each pass by k_scanc
__device__ int   g_rowptr[NN + 1];
__device__ int   g_cursor[NN];
__device__ int   g_bsum[NB_SCAN];
__device__ int   g_boff[NB_SCAN];
__device__ unsigned short g_col[EE];
__device__ float g_bufA[NN * HH];      // xw1_scaled, then reused as gather source L1
__device__ float g_bufB[NN * HH];      // xw2_scaled (gemm2 fused into agg1)

// ---------------- histogram: 4 edges / thread ----------------
__global__ void k_hist(const int* __restrict__ ei) {
    int e = (blockIdx.x * blockDim.x + threadIdx.x) * 4;
    if (e >= EE) return;
    int4 d = *(const int4*)(ei + EE + e);
    atomicAdd(&g_count[d.x], 1);
    atomicAdd(&g_count[d.y], 1);
    atomicAdd(&g_count[d.z], 1);
    atomicAdd(&g_count[d.w], 1);
}

// ---------------- parallel scan: reduce -> scan sums -> scan blocks ----
__global__ void __launch_bounds__(1024) k_red() {
    __shared__ int sred[32];
    int t = threadIdx.x, lane = t & 31, w = t >> 5;
    int i = blockIdx.x * 1024 + t;
    int v = (i < NN) ? g_count[i] : 0;
    #pragma unroll
    for (int o = 16; o; o >>= 1) v += __shfl_down_sync(0xffffffffu, v, o);
    if (lane == 0) sred[w] = v;
    __syncthreads();
    if (w == 0) {
        int s = sred[lane];
        #pragma unroll
        for (int o = 16; o; o >>= 1) s += __shfl_down_sync(0xffffffffu, s, o);
        if (lane == 0) g_bsum[blockIdx.x] = s;
    }
}

__global__ void k_scanb() {   // 1 block, 32 threads; NB_SCAN <= 64
    int lane = threadIdx.x;
    int a = (lane < NB_SCAN) ? g_bsum[lane] : 0;
    int b = (lane + 32 < NB_SCAN) ? g_bsum[lane + 32] : 0;
    int sa = a, sb = b;
    #pragma unroll
    for (int o = 1; o < 32; o <<= 1) {
        int y = __shfl_up_sync(0xffffffffu, sa, o);
        if (lane >= o) sa += y;
    }
    int tot_a = __shfl_sync(0xffffffffu, sa, 31);
    #pragma unroll
    for (int o = 1; o < 32; o <<= 1) {
        int y = __shfl_up_sync(0xffffffffu, sb, o);
        if (lane >= o) sb += y;
    }
    sb += tot_a;
    g_boff[lane] = sa - a;
    if (lane + 32 < NB_SCAN) g_boff[lane + 32] = sb - b;
    if (lane == 31) g_rowptr[NN] = sb;      // grand total
}

__global__ void __launch_bounds__(1024) k_scanc() {
    __shared__ int wsum[32];
    int t = threadIdx.x, lane = t & 31, w = t >> 5;
    int i = blockIdx.x * 1024 + t;
    int v = (i < NN) ? g_count[i] : 0;
    int incl = v;
    #pragma unroll
    for (int o = 1; o < 32; o <<= 1) {
        int y = __shfl_up_sync(0xffffffffu, incl, o);
        if (lane >= o) incl += y;
    }
    if (lane == 31) wsum[w] = incl;
    __syncthreads();
    if (w == 0) {
        int s = wsum[lane];
        #pragma unroll
        for (int o = 1; o < 32; o <<= 1) {
            int y = __shfl_up_sync(0xffffffffu, s, o);
            if (lane >= o) s += y;
        }
        wsum[lane] = s;
    }
    __syncthreads();
    int base = g_boff[blockIdx.x] + ((w > 0) ? wsum[w - 1] : 0);
    int excl = base + incl - v;
    if (i < NN) {
        g_rowptr[i] = excl;
        g_cursor[i] = excl;
        g_dinv[i]   = rsqrtf((float)(v + 1));   // +1 self loop
        g_count[i]  = 0;                        // reset for next replay
    }
}

// ---------------- scatter: 4 edges / thread, uint16 cols ----------------
__global__ void k_scatter(const int* __restrict__ ei) {
    int e = (blockIdx.x * blockDim.x + threadIdx.x) * 4;
    if (e >= EE) return;
    int4 s = *(const int4*)(ei + e);
    int4 d = *(const int4*)(ei + EE + e);
    int p0 = atomicAdd(&g_cursor[d.x], 1);
    int p1 = atomicAdd(&g_cursor[d.y], 1);
    int p2 = atomicAdd(&g_cursor[d.z], 1);
    int p3 = atomicAdd(&g_cursor[d.w], 1);
    g_col[p0] = (unsigned short)s.x;
    g_col[p1] = (unsigned short)s.y;
    g_col[p2] = (unsigned short)s.z;
    g_col[p3] = (unsigned short)s.w;
}

// ---------------- GEMM1: bufA = (x @ W1) * dinv, register-tiled ----------------
// 256 rows/block, 256 threads, thread tile 8 rows x 4 cols.
__global__ void __launch_bounds__(256) k_gemm1(const float* __restrict__ x,
                                               const float* __restrict__ W1) {
    __shared__ float sW[FIN][HH + 1];     // 128x33
    __shared__ float sx[256][36];         // 256 rows x 32 k (padded, 16B-aligned stride)
    int tid = threadIdx.x;
    for (int i = tid; i < FIN * HH; i += 256) sW[i >> 5][i & 31] = W1[i];
    int c4 = (tid & 7) * 4;               // col group
    int rg = tid >> 3;                    // row group 0..31 (8 rows each)
    int row0 = blockIdx.x * 256;
    float acc[8][4];
    #pragma unroll
    for (int r = 0; r < 8; r++)
        #pragma unroll
        for (int j = 0; j < 4; j++) acc[r][j] = 0.f;

    for (int kc = 0; kc < FIN; kc += 32) {
        __syncthreads();
        #pragma unroll
        for (int i = tid; i < 256 * 8; i += 256) {   // one float4 each iter
            int r = i >> 3, kq = (i & 7) * 4;
            int rr = row0 + r; if (rr >= NN) rr = NN - 1;
            float4 v = *(const float4*)(x + (size_t)rr * FIN + kc + kq);
            *(float4*)&sx[r][kq] = v;
        }
        __syncthreads();
        #pragma unroll
        for (int k = 0; k < 32; k += 4) {
            float w[4][4];
            #pragma unroll
            for (int kk = 0; kk < 4; kk++)
                #pragma unroll
                for (int j = 0; j < 4; j++) w[kk][j] = sW[kc + k + kk][c4 + j];
            #pragma unroll
            for (int r = 0; r < 8; r++) {
                float4 xv = *(float4*)&sx[rg * 8 + r][k];
                #pragma unroll
                for (int j = 0; j < 4; j++)
                    acc[r][j] += xv.x * w[0][j] + xv.y * w[1][j]
                               + xv.z * w[2][j] + xv.w * w[3][j];
            }
        }
    }
    #pragma unroll
    for (int r = 0; r < 8; r++) {
        int row = row0 + rg * 8 + r;
        if (row < NN) {
            float dv = g_dinv[row];
            float4 o = make_float4(acc[r][0] * dv, acc[r][1] * dv,
                                   acc[r][2] * dv, acc[r][3] * dv);
            *(float4*)(g_bufA + row * HH + c4) = o;
        }
    }
}

// ---------------- aggregation core (warp per node) ----------------
__device__ __forceinline__ float agg_node(const float* __restrict__ src, int i, int lane) {
    const int* __restrict__ rp = g_rowptr;
    const unsigned short* __restrict__ col = g_col;
    int beg = rp[i], end = rp[i + 1];
    float acc = src[i * HH + lane];        // self loop (dinv[src] folded in)
    int e = beg;
    while (end - e >= 32) {
        int idx = col[e + lane];
        float a0 = 0.f, a1 = 0.f, a2 = 0.f, a3 = 0.f;
        #pragma unroll
        for (int k = 0; k < 32; k += 4) {
            int s0 = __shfl_sync(0xffffffffu, idx, k);
            int s1 = __shfl_sync(0xffffffffu, idx, k + 1);
            int s2 = __shfl_sync(0xffffffffu, idx, k + 2);
            int s3 = __shfl_sync(0xffffffffu, idx, k + 3);
            a0 += src[s0 * HH + lane];
            a1 += src[s1 * HH + lane];
            a2 += src[s2 * HH + lane];
            a3 += src[s3 * HH + lane];
        }
        acc += (a0 + a1) + (a2 + a3);
        e += 32;
    }
    int m = end - e;
    if (m > 0) {
        int idx = (lane < m) ? (int)col[e + lane] : 0;
        for (int k = 0; k < m; k++) {
            int s = __shfl_sync(0xffffffffu, idx, k);
            acc += src[s * HH + lane];
        }
    }
    return acc;
}

// layer1 aggregate + tanh + FUSED gemm2: bufB = (tanh(...) @ W2) * dinv
__global__ void __launch_bounds__(256) k_agg1(const float* __restrict__ b1,
                                              const float* __restrict__ W2) {
    __shared__ float sW[HH * HH];
    int t = threadIdx.x;
    for (int i = t; i < HH * HH; i += 256) sW[i] = W2[i];
    __syncthreads();
    int warp = (blockIdx.x * 256 + t) >> 5;
    int lane = t & 31;
    if (warp >= NN) return;
    float acc = agg_node(g_bufA, warp, lane);
    float dv  = g_dinv[warp];
    float h   = tanhf(dv * acc + b1[lane]);
    float o   = 0.f;
    #pragma unroll
    for (int k = 0; k < HH; k++)
        o += __shfl_sync(0xffffffffu, h, k) * sW[k * HH + lane];
    g_bufB[warp * HH + lane] = o * dv;
}

// layer2 aggregate + tanh + fused classifier. out = [ logits (NN*CC) | h (NN*HH) ]
__global__ void __launch_bounds__(256) k_agg2(const float* __restrict__ b2,
                                              const float* __restrict__ Wc,
                                              const float* __restrict__ bc,
                                              float* __restrict__ out) {
    __shared__ float sWc[HH * CC];
    __shared__ float sbc[CC];
    int t = threadIdx.x;
    for (int i = t; i < HH * CC; i += 256) sWc[i] = Wc[i];
    if (t < CC) sbc[t] = bc[t];
    __syncthreads();
    int warp = (blockIdx.x * 256 + t) >> 5;
    int lane = t & 31;
    if (warp >= NN) return;
    float acc = agg_node(g_bufB, warp, lane);
    float h = tanhf(g_dinv[warp] * acc + b2[lane]);
    out[NN * CC + warp * HH + lane] = h;
    float o = 0.f;
    int c = lane & 15;
    #pragma unroll
    for (int k = 0; k < HH; k++) {
        float hk = __shfl_sync(0xffffffffu, h, k);
        o += hk * sWc[k * CC + c];
    }
    if (lane < CC) out[warp * CC + lane] = o + sbc[lane];
}

// ---------------- launch ----------------
extern "C" void kernel_launch(void* const* d_in, const int* in_sizes, int n_in,
                              void* d_out, int out_size) {
    const float* x  = (const float*)d_in[0];
    const int*   ei = (const int*)  d_in[1];
    const float* W1 = (const float*)d_in[2];
    const float* b1 = (const float*)d_in[3];
    const float* W2 = (const float*)d_in[4];
    const float* b2 = (const float*)d_in[5];
    const float* Wc = (const float*)d_in[6];
    const float* bc = (const float*)d_in[7];
    float* out = (float*)d_out;

    k_hist   <<<(EE / 4 + 255) / 256, 256>>>(ei);
    k_red    <<<NB_SCAN, 1024>>>();
    k_scanb  <<<1, 32>>>();
    k_scanc  <<<NB_SCAN, 1024>>>();
    k_scatter<<<(EE / 4 + 255) / 256, 256>>>(ei);
    k_gemm1  <<<(NN + 255) / 256, 256>>>(x, W1);
    k_agg1   <<<(NN * 32 + 255) / 256, 256>>>(b1, W2);
    k_agg2   <<<(NN * 32 + 255) / 256, 256>>>(b2, Wc, bc, out);
}